// round 6
// baseline (speedup 1.0000x reference)
#include <cuda_runtime.h>

#define Bc 4
#define Nc 2048
#define Dc 64
#define NSLAB 16
#define CPS (Nc / NSLAB)          // columns per slab = 128 (2 tiles of 64)
#define SAMBLK (Bc * Nc / 8)      // 1024 k_sam blocks

// ---------------- device scratch (no allocations allowed) ----------------
__device__ float  g_nf[Bc * Nc * Dc];            // normalized features
__device__ float4 g_meta[Bc * Nc * 3];           // (ux,uy,uz,c0) (c1,c2,px,py) (pz,label,mask,0)
__device__ float  g_accp[NSLAB * Bc * Nc * 9];   // per-slab per-row partials
__device__ float4 g_blockloss[SAMBLK];           // per-k_sam-block (wloss,m,nll,valid) sums
__device__ unsigned int g_ctr;                   // last-block counter (wraps -> deterministic)

__device__ __forceinline__ float sqrt_approx(float x) {
    float r; asm("sqrt.approx.f32 %0, %1;" : "=f"(r) : "f"(x)); return r;
}
__device__ __forceinline__ float ex2_approx(float x) {
    float r; asm("ex2.approx.f32 %0, %1;" : "=f"(r) : "f"(x)); return r;
}
__device__ __forceinline__ float rcp_approx(float x) {
    float r; asm("rcp.approx.f32 %0, %1;" : "=f"(r) : "f"(x)); return r;
}
__device__ __forceinline__ float tanh_approx(float x) {
    float r; asm("tanh.approx.f32 %0, %1;" : "=f"(r) : "f"(x)); return r;
}
__device__ __forceinline__ void fma2(unsigned long long& d, unsigned long long a,
                                     unsigned long long b) {
    asm("fma.rn.f32x2 %0, %1, %2, %0;" : "+l"(d) : "l"(a), "l"(b));
}
__device__ __forceinline__ unsigned long long pk(float x, float y) {
    unsigned long long r; asm("mov.b64 %0, {%1,%2};" : "=l"(r) : "f"(x), "f"(y)); return r;
}
__device__ __forceinline__ float2 upk(unsigned long long v) {
    float2 r; asm("mov.b64 {%0,%1}, %2;" : "=f"(r.x), "=f"(r.y) : "l"(v)); return r;
}
#define L2E 1.4426950408889634f

// ---------------- kernel 1: per-point precompute ----------------
__global__ void k_prep(const float* __restrict__ feat, const float* __restrict__ flow,
                       const float* __restrict__ pts, const int* __restrict__ colors,
                       const int* __restrict__ sam, const unsigned char* __restrict__ mask) {
    int p = blockIdx.x * blockDim.x + threadIdx.x;
    if (p >= Bc * Nc) return;
    const float4* f = (const float4*)(feat + (size_t)p * Dc);
    float4 buf[16];
    float ss = 0.f;
#pragma unroll
    for (int i = 0; i < 16; i++) {
        float4 v = f[i]; buf[i] = v;
        ss += v.x * v.x + v.y * v.y + v.z * v.z + v.w * v.w;
    }
    float inv = __fdividef(1.f, sqrtf(ss) + 1e-7f);
    float4* o = (float4*)(g_nf + (size_t)p * Dc);
#pragma unroll
    for (int i = 0; i < 16; i++) {
        float4 v = buf[i];
        v.x *= inv; v.y *= inv; v.z *= inv; v.w *= inv;
        o[i] = v;
    }
    float fx = flow[p * 3 + 0], fy = flow[p * 3 + 1], fz = flow[p * 3 + 2];
    float fn = sqrtf(fx * fx + fy * fy + fz * fz);
    float fi = __fdividef(1.f, fmaxf(fn, 1e-20f));
    const float ic = 1.f / 255.f;
    float c0 = colors[p * 3 + 0] * ic, c1 = colors[p * 3 + 1] * ic, c2 = colors[p * 3 + 2] * ic;
    float px = pts[p * 3 + 0], py = pts[p * 3 + 1], pz = pts[p * 3 + 2];
    g_meta[p * 3 + 0] = make_float4(fx * fi, fy * fi, fz * fi, c0);
    g_meta[p * 3 + 1] = make_float4(c1, c2, px, py);
    g_meta[p * 3 + 2] = make_float4(pz, (float)sam[p], mask[p] ? 1.f : 0.f, 0.f);
}

// ---------------- pairwise elementwise math ----------------
__device__ __forceinline__ void ew_loss(float fsl, float s, float tau, float enf,
                                        float& ap, float& am) {
    float th = tanh_approx(2.5f * (s - tau));
    float gp = fmaf(0.5f, th, 0.5f);
    float e1 = ex2_approx(fsl * gp);
    ap += e1;
    am += e1 * enf;
}

__device__ __forceinline__ void pair_ew(float fs,
    const float4& ra, const float4& rb, const float4& rc,
    const float4& ca, const float4& cb, const float4& cc,
    float* acc) {
    float mm = rc.z * cc.z;  // mask outer product
    float sflow = (ra.x * ca.x + ra.y * ca.y + ra.z * ca.z) * mm;
    float dx = ra.w - ca.w, dy = rb.x - cb.x, dz = rb.y - cb.y;
    float scol = (1.f - sqrt_approx(dx * dx + dy * dy + dz * dz) * 0.5773502691896258f) * mm;
    float qx = rb.z - cb.z, qy = rb.w - cb.w, qz = rc.x - cc.x;
    float sprox = ex2_approx(sqrt_approx(qx * qx + qy * qy + qz * qz) * (-50.f * L2E)) * mm;

    float fsl = fs * L2E;
    float enf = ex2_approx(-fsl);        // exp(-fs)
    float ef  = rcp_approx(enf);         // exp(+fs)
    ew_loss(fsl, sflow, 0.8f, enf, acc[0], acc[1]);
    ew_loss(fsl, scol,  0.7f, enf, acc[2], acc[3]);
    ew_loss(fsl, sprox, 0.5f, enf, acc[4], acc[5]);
    acc[6] += ef;
    if (rc.y == cc.y) {
        acc[7] += ef;
        acc[8] += 1.f;
    }
}

// ---------------- kernel 2: main N^2 pair loop ----------------
// grid (Nc/64, Bc, NSLAB), block 256. Block tile: 64 rows x 128 cols, both col
// tiles resident in smem; single dot phase for D[2][4][4], then one ew pass over
// 32 independent pairs (deep MUFU ILP). Dynamic smem: 61440 B.
#define SSTR 68   // padded smem row stride (floats)

__global__ void __launch_bounds__(256, 2) k_pairs() {
    extern __shared__ float sm[];
    float* sA = sm;                          // 64 rows
    float* sB = sm + 64 * SSTR;              // 128 rows
    float4* sMA = (float4*)(sm + 192 * SSTR);
    float4* sMB = sMA + 192;

    int b = blockIdx.y, rt = blockIdx.x, slab = blockIdx.z;
    int tid = threadIdx.x, tx = tid & 15, ty = tid >> 4;
    int rowbase = b * Nc + rt * 64;
    int colbase = b * Nc + slab * CPS;

    {
        const float4* srcA = (const float4*)(g_nf + (size_t)rowbase * Dc);
#pragma unroll
        for (int j = tid; j < 1024; j += 256) {
            float4 v = srcA[j];
            ((float4*)(sA + (j >> 4) * SSTR))[j & 15] = v;
        }
        const float4* srcB = (const float4*)(g_nf + (size_t)colbase * Dc);
#pragma unroll
        for (int j = tid; j < 2048; j += 256) {
            float4 v = srcB[j];
            ((float4*)(sB + (j >> 4) * SSTR))[j & 15] = v;
        }
        if (tid < 192) sMA[tid] = ((const float4*)&g_meta[(size_t)rowbase * 3])[tid];
#pragma unroll
        for (int j = tid; j < 384; j += 256)
            sMB[j] = ((const float4*)&g_meta[(size_t)colbase * 3])[j];
    }
    __syncthreads();

    unsigned long long D[2][4][4];
#pragma unroll
    for (int t = 0; t < 2; t++)
#pragma unroll
        for (int i = 0; i < 4; i++)
#pragma unroll
            for (int j = 0; j < 4; j++) D[t][i][j] = 0ull;

#pragma unroll
    for (int kc = 0; kc < 16; kc++) {
        unsigned long long alo[4], ahi[4];
#pragma unroll
        for (int i = 0; i < 4; i++) {
            float4 av = ((const float4*)(sA + (ty + 16 * i) * SSTR))[kc];
            alo[i] = pk(av.x, av.y); ahi[i] = pk(av.z, av.w);
        }
#pragma unroll
        for (int t = 0; t < 2; t++)
#pragma unroll
            for (int j = 0; j < 4; j++) {
                float4 bv = ((const float4*)(sB + (tx + 16 * j + 64 * t) * SSTR))[kc];
                unsigned long long bl = pk(bv.x, bv.y), bh = pk(bv.z, bv.w);
#pragma unroll
                for (int i = 0; i < 4; i++) {
                    fma2(D[t][i][j], alo[i], bl);
                    fma2(D[t][i][j], ahi[i], bh);
                }
            }
    }

    float acc[4][9];
#pragma unroll
    for (int i = 0; i < 4; i++)
#pragma unroll
        for (int j = 0; j < 9; j++) acc[i][j] = 0.f;

#pragma unroll
    for (int t = 0; t < 2; t++)
#pragma unroll
        for (int j = 0; j < 4; j++) {
            int c = tx + 16 * j + 64 * t;
            float4 ca = sMB[c * 3 + 0], cb = sMB[c * 3 + 1], cc = sMB[c * 3 + 2];
#pragma unroll
            for (int i = 0; i < 4; i++) {
                int r = ty + 16 * i;
                float4 ra = sMA[r * 3 + 0], rb = sMA[r * 3 + 1], rc = sMA[r * 3 + 2];
                float2 dv = upk(D[t][i][j]);
                pair_ew(dv.x + dv.y, ra, rb, rc, ca, cb, cc, acc[i]);
            }
        }

    // reduce each row's partials across the 16 tx lanes
    float* slabbase = g_accp + (size_t)slab * Bc * Nc * 9;
#pragma unroll
    for (int i = 0; i < 4; i++) {
#pragma unroll
        for (int j = 0; j < 9; j++) {
            float v = acc[i][j];
#pragma unroll
            for (int o = 8; o >= 1; o >>= 1)
                v += __shfl_xor_sync(0xffffffffu, v, o);
            if (tx == 0)
                slabbase[(size_t)(rowbase + ty + 16 * i) * 9 + j] = v;
        }
    }
}

// ---------------- kernel 3: SAM pass + per-row finalize + fused final reduce ---
__global__ void __launch_bounds__(256) k_sam(const int* __restrict__ sam,
                                             float* __restrict__ out) {
    int wl = threadIdx.x >> 5, lane = threadIdx.x & 31;
    int gw = blockIdx.x * 8 + wl;                 // global row id; 8 rows/block, same batch
    int b = (blockIdx.x * 8) >> 11;
    __shared__ int slabels[Nc];
    __shared__ float4 sf[8][16];
    __shared__ float4 srow[8];
    __shared__ bool islast;
    const int* samb = sam + b * Nc;
    for (int i = threadIdx.x; i < Nc; i += 256) slabels[i] = samb[i];
    if (lane < 16) sf[wl][lane] = ((const float4*)(g_nf + (size_t)gw * Dc))[lane];
    __syncthreads();

    float aj = 0.f;
    if (lane < 9) {
#pragma unroll
        for (int s = 0; s < NSLAB; s++)
            aj += g_accp[((size_t)s * Bc * Nc + gw) * 9 + lane];
    }
    float a0 = __shfl_sync(0xffffffffu, aj, 0);
    float a1 = __shfl_sync(0xffffffffu, aj, 1);
    float a2 = __shfl_sync(0xffffffffu, aj, 2);
    float a3 = __shfl_sync(0xffffffffu, aj, 3);
    float a4 = __shfl_sync(0xffffffffu, aj, 4);
    float a5 = __shfl_sync(0xffffffffu, aj, 5);
    float Sall = __shfl_sync(0xffffffffu, aj, 6);
    float Spos = __shfl_sync(0xffffffffu, aj, 7);
    float P    = __shfl_sync(0xffffffffu, aj, 8);
    float Sneg = Sall - Spos;

    int lbl = slabels[gw - b * Nc];
    float acc = 0.f;
    for (int m = lane; m < Nc; m += 32) {
        if (slabels[m] == lbl) {
            const float4* fm = (const float4*)(g_nf + (size_t)(b * Nc + m) * Dc);
            float fs = 0.f;
#pragma unroll
            for (int k = 0; k < 16; k++) {
                float4 x = sf[wl][k]; float4 y = fm[k];
                fs += x.x * y.x + x.y * y.y + x.z * y.z + x.w * y.w;
            }
            acc += __logf(__expf(fs) + Sneg) - fs;
        }
    }
#pragma unroll
    for (int o = 16; o >= 1; o >>= 1) acc += __shfl_xor_sync(0xffffffffu, acc, o);

    if (lane == 0) {
        float m = g_meta[(size_t)gw * 3 + 2].z;
        float wloss = m * (log1pf(a0) + log1pf(a1) + log1pf(a2) +
                           log1pf(a3) + log1pf(a4) + log1pf(a5));
        float valid = P > 0.f ? 1.f : 0.f;
        float nll = acc / fmaxf(P, 1e-6f);
        srow[wl] = make_float4(wloss, m, nll * valid, valid);
    }
    __syncthreads();
    if (threadIdx.x == 0) {
        float4 s = srow[0];
#pragma unroll
        for (int j = 1; j < 8; j++) {
            float4 v = srow[j];
            s.x += v.x; s.y += v.y; s.z += v.z; s.w += v.w;
        }
        g_blockloss[blockIdx.x] = s;
    }
    __threadfence();
    if (threadIdx.x == 0)
        islast = (atomicInc(&g_ctr, SAMBLK - 1) == SAMBLK - 1);
    __syncthreads();
    if (!islast) return;

    // last block: reduce 1024 float4 (256 entries per batch). thread t handles
    // entries 4t..4t+3 (all batch t>>6); warp w covers half of batch w>>1.
    int t = threadIdx.x;
    float s0 = 0.f, s1 = 0.f, s2 = 0.f, s3 = 0.f;
#pragma unroll
    for (int k = 0; k < 4; k++) {
        float4 v = __ldcg(&g_blockloss[4 * t + k]);
        s0 += v.x; s1 += v.y; s2 += v.z; s3 += v.w;
    }
#pragma unroll
    for (int o = 16; o >= 1; o >>= 1) {
        s0 += __shfl_xor_sync(0xffffffffu, s0, o);
        s1 += __shfl_xor_sync(0xffffffffu, s1, o);
        s2 += __shfl_xor_sync(0xffffffffu, s2, o);
        s3 += __shfl_xor_sync(0xffffffffu, s3, o);
    }
    __shared__ float4 wred[8];
    if (lane == 0) wred[t >> 5] = make_float4(s0, s1, s2, s3);
    __syncthreads();
    if (t == 0) {
        float tot = 0.f;
        for (int bb = 0; bb < Bc; bb++) {
            float4 u = wred[2 * bb], v = wred[2 * bb + 1];
            float p0 = u.x + v.x, p1 = u.y + v.y, p2 = u.z + v.z, p3 = u.w + v.w;
            tot += -p0 / p1 + p2 / fmaxf(p3, 1e-6f);
        }
        out[0] = tot * (1.f / Bc);
    }
}

// ---------------- launcher ----------------
extern "C" void kernel_launch(void* const* d_in, const int* in_sizes, int n_in,
                              void* d_out, int out_size) {
    const float* feat         = (const float*)d_in[0];
    const float* flow         = (const float*)d_in[1];
    const float* pts          = (const float*)d_in[2];
    const int* colors         = (const int*)d_in[3];
    const int* sam            = (const int*)d_in[4];
    const unsigned char* mask = (const unsigned char*)d_in[5];

    const int smemBytes = (192 * SSTR) * 4 + 576 * 16;   // 61440
    cudaFuncSetAttribute(k_pairs, cudaFuncAttributeMaxDynamicSharedMemorySize, smemBytes);

    k_prep<<<(Bc * Nc + 127) / 128, 128>>>(feat, flow, pts, colors, sam, mask);
    dim3 grid(Nc / 64, Bc, NSLAB);
    k_pairs<<<grid, 256, smemBytes>>>();
    k_sam<<<SAMBLK, 256>>>(sam, (float*)d_out);
}